// round 4
// baseline (speedup 1.0000x reference)
#include <cuda_runtime.h>
#include <cstdint>

#define CODE_DIM 64
#define IN_DIM   68
#define HID      128
#define DT_MAXF  0.125f
#define NSTEPS   8
#define THREADS  384
#define NWARPS   (THREADS/32)          // 12
#define PPW      8
#define PPB      (NWARPS*PPW)          // 96 points per block
#define MAXN     (1<<18)

typedef unsigned long long ull;

// ---- scratch for bucketing (no allocs allowed) ----
__device__ int g_hist[16];
__device__ int g_cursor[16];
__device__ int g_perm[MAXN];

// ---- shared memory layout (float offsets), 16B-aligned ----
#define SM_W1   0
#define SM_B1   (SM_W1 + IN_DIM*HID)          // 8704
#define SM_W2   (SM_B1 + HID)                 // 8832
#define SM_B2   (SM_W2 + HID*HID)             // 25216
#define SM_W3   (SM_B2 + HID)                 // 25344, padded [128][4]
#define SM_B3   (SM_W3 + HID*4)               // 25856
#define SM_CODE (SM_B3 + 4)                   // 25860, [k][point-in-block]
#define SM_STG  (SM_CODE + CODE_DIM*PPB)      // per-warp [k][8] (holds h1 after fwd)
#define SM_DSTG (SM_STG + NWARPS*HID*PPW)     // per-warp [k][8] (dh1 staging)
#define SM_WX   (SM_DSTG + NWARPS*HID*PPW)    // per-warp [4][8]
#define SM_TOTAL (SM_WX + NWARPS*4*PPW)       // 56964 floats = 227856 B

__device__ __forceinline__ float ftanh(float x){
    float e = __expf(2.0f * x);
    return 1.0f - __fdividef(2.0f, e + 1.0f);
}
__device__ __forceinline__ ull ffma2(ull a, ull b, ull c){
    ull d; asm("fma.rn.f32x2 %0, %1, %2, %3;" : "=l"(d) : "l"(a), "l"(b), "l"(c)); return d;
}
__device__ __forceinline__ ull pack2(float lo, float hi){
    ull d; asm("mov.b64 %0, {%1, %2};" : "=l"(d) : "f"(lo), "f"(hi)); return d;
}
__device__ __forceinline__ void unpack2(ull v, float& lo, float& hi){
    asm("mov.b64 {%0, %1}, %2;" : "=f"(lo), "=f"(hi) : "l"(v));
}

__device__ __forceinline__ void fma_step8(ull acc[4][4],
        const float* __restrict__ xrow, const float* __restrict__ wrow){
    ulonglong2 xa = *(const ulonglong2*)(xrow);
    ulonglong2 xb = *(const ulonglong2*)(xrow + 4);
    float4 wv = *(const float4*)(wrow);
    ull wd0 = pack2(wv.x, wv.x), wd1 = pack2(wv.y, wv.y);
    ull wd2 = pack2(wv.z, wv.z), wd3 = pack2(wv.w, wv.w);
    ull xp0 = xa.x, xp1 = xa.y, xp2 = xb.x, xp3 = xb.y;
    acc[0][0]=ffma2(xp0,wd0,acc[0][0]); acc[0][1]=ffma2(xp0,wd1,acc[0][1]);
    acc[0][2]=ffma2(xp0,wd2,acc[0][2]); acc[0][3]=ffma2(xp0,wd3,acc[0][3]);
    acc[1][0]=ffma2(xp1,wd0,acc[1][0]); acc[1][1]=ffma2(xp1,wd1,acc[1][1]);
    acc[1][2]=ffma2(xp1,wd2,acc[1][2]); acc[1][3]=ffma2(xp1,wd3,acc[1][3]);
    acc[2][0]=ffma2(xp2,wd0,acc[2][0]); acc[2][1]=ffma2(xp2,wd1,acc[2][1]);
    acc[2][2]=ffma2(xp2,wd2,acc[2][2]); acc[2][3]=ffma2(xp2,wd3,acc[2][3]);
    acc[3][0]=ffma2(xp3,wd0,acc[3][0]); acc[3][1]=ffma2(xp3,wd1,acc[3][1]);
    acc[3][2]=ffma2(xp3,wd2,acc[3][2]); acc[3][3]=ffma2(xp3,wd3,acc[3][3]);
}

__device__ __forceinline__ void gemm_h8(const float* __restrict__ src,
        const float* __restrict__ W2s, int i4, ull acc[4][4]){
#pragma unroll 4
    for (int k = 0; k < HID; k++)
        fma_step8(acc, src + k*PPW, W2s + k*HID + i4);
}

__device__ __forceinline__ void acc_init_bias(ull acc[4][4], const float* bs, int i4){
    float4 bv = *(const float4*)(bs + i4);
    ull b0 = pack2(bv.x,bv.x), b1 = pack2(bv.y,bv.y);
    ull b2 = pack2(bv.z,bv.z), b3 = pack2(bv.w,bv.w);
#pragma unroll
    for (int pp = 0; pp < 4; pp++){ acc[pp][0]=b0; acc[pp][1]=b1; acc[pp][2]=b2; acc[pp][3]=b3; }
}

__device__ __forceinline__ void reduce24(float sv[24]){
#pragma unroll
    for (int o = 16; o > 0; o >>= 1)
#pragma unroll
        for (int q = 0; q < 24; q++)
            sv[q] += __shfl_xor_sync(0xffffffffu, sv[q], o);
}

__device__ __forceinline__ void extract3(const float sv[24], int lane,
                                         float& x, float& y, float& z){
    x = 0.f; y = 0.f; z = 0.f;
#pragma unroll
    for (int p = 0; p < 8; p++){
        bool s = (lane == p);
        x = s ? sv[p*3+0] : x;
        y = s ? sv[p*3+1] : y;
        z = s ? sv[p*3+2] : z;
    }
}

// forward MLP for 8 points. Leaves h1 staged in stg (layout [k][8]).
// Returns g2 = 1 - h2^2 (for tangent passes) and owner-extracted velocity.
__device__ __forceinline__ void mlp_fwd8(const float* __restrict__ sm,
        float* __restrict__ stg, const float* __restrict__ wx,
        int i4, int cbase, int lane,
        float g2[8][4],
        float b3x, float b3y, float b3z,
        float& vx, float& vy, float& vz)
{
    const float* W1s = sm + SM_W1;
    const float* W2s = sm + SM_W2;
    const float* W3s = sm + SM_W3;
    const float* codes = sm + SM_CODE;

    ull acc[4][4];
    acc_init_bias(acc, sm + SM_B1, i4);
#pragma unroll 4
    for (int k = 0; k < CODE_DIM; k++)
        fma_step8(acc, codes + k*PPB + cbase, W1s + k*HID + i4);
#pragma unroll
    for (int kk = 0; kk < 4; kk++)
        fma_step8(acc, wx + kk*PPW, W1s + (CODE_DIM+kk)*HID + i4);

    // tanh + stage h1 directly to stg, column-wise (low live-range)
    __syncwarp();
#pragma unroll
    for (int c = 0; c < 4; c++){
        float h0, h1v, h2v, h3, h4, h5, h6, h7;
        { float a,b; unpack2(acc[0][c],a,b); h0=ftanh(a); h1v=ftanh(b); }
        { float a,b; unpack2(acc[1][c],a,b); h2v=ftanh(a); h3=ftanh(b); }
        { float a,b; unpack2(acc[2][c],a,b); h4=ftanh(a); h5=ftanh(b); }
        { float a,b; unpack2(acc[3][c],a,b); h6=ftanh(a); h7=ftanh(b); }
        *(float4*)(stg + (i4+c)*PPW)     = make_float4(h0,h1v,h2v,h3);
        *(float4*)(stg + (i4+c)*PPW + 4) = make_float4(h4,h5,h6,h7);
    }
    __syncwarp();

    acc_init_bias(acc, sm + SM_B2, i4);
    gemm_h8(stg, W2s, i4, acc);

    // h2 = tanh(acc); use for output layer, then convert to g2 = 1 - h2^2
    float h2r[8][4];
#pragma unroll
    for (int pp = 0; pp < 4; pp++)
#pragma unroll
        for (int c = 0; c < 4; c++){
            float a, b; unpack2(acc[pp][c], a, b);
            h2r[2*pp  ][c] = ftanh(a);
            h2r[2*pp+1][c] = ftanh(b);
        }

    float sv[24];
#pragma unroll
    for (int q = 0; q < 24; q++) sv[q] = 0.f;
#pragma unroll
    for (int c = 0; c < 4; c++){
        float4 w3 = *(const float4*)(W3s + (i4+c)*4);
#pragma unroll
        for (int p = 0; p < 8; p++){
            sv[p*3+0] = fmaf(h2r[p][c], w3.x, sv[p*3+0]);
            sv[p*3+1] = fmaf(h2r[p][c], w3.y, sv[p*3+1]);
            sv[p*3+2] = fmaf(h2r[p][c], w3.z, sv[p*3+2]);
        }
    }
#pragma unroll
    for (int p = 0; p < 8; p++)
#pragma unroll
        for (int c = 0; c < 4; c++)
            g2[p][c] = fmaf(-h2r[p][c], h2r[p][c], 1.0f);

    reduce24(sv);
    extract3(sv, lane, vx, vy, vz);
    vx += b3x; vy += b3y; vz += b3z;
}

// tangent wrt x_j. h1 is read back from stg; dh1 staged into dstg.
__device__ __forceinline__ void mlp_tan8(const float* __restrict__ sm,
        const float* __restrict__ stg, float* __restrict__ dstg,
        int i4, int j, int lane, const float g2[8][4],
        float& jx, float& jy, float& jz)
{
    const float* W1s = sm + SM_W1;
    const float* W2s = sm + SM_W2;
    const float* W3s = sm + SM_W3;

    float4 wr = *(const float4*)(W1s + (CODE_DIM + j)*HID + i4);
    float wc[4] = {wr.x, wr.y, wr.z, wr.w};

    __syncwarp();   // previous gemm readers of dstg done
#pragma unroll
    for (int c = 0; c < 4; c++){
        float4 ha = *(const float4*)(stg + (i4+c)*PPW);     // h1, this lane's column
        float4 hb = *(const float4*)(stg + (i4+c)*PPW + 4);
        float4 da, db;
        da.x = fmaf(-ha.x, ha.x*wc[c], wc[c]);
        da.y = fmaf(-ha.y, ha.y*wc[c], wc[c]);
        da.z = fmaf(-ha.z, ha.z*wc[c], wc[c]);
        da.w = fmaf(-ha.w, ha.w*wc[c], wc[c]);
        db.x = fmaf(-hb.x, hb.x*wc[c], wc[c]);
        db.y = fmaf(-hb.y, hb.y*wc[c], wc[c]);
        db.z = fmaf(-hb.z, hb.z*wc[c], wc[c]);
        db.w = fmaf(-hb.w, hb.w*wc[c], wc[c]);
        *(float4*)(dstg + (i4+c)*PPW)     = da;
        *(float4*)(dstg + (i4+c)*PPW + 4) = db;
    }
    __syncwarp();

    ull acc[4][4];
    ull z = pack2(0.f, 0.f);
#pragma unroll
    for (int pp = 0; pp < 4; pp++)
#pragma unroll
        for (int c = 0; c < 4; c++) acc[pp][c] = z;
    gemm_h8(dstg, W2s, i4, acc);

    float sv[24];
#pragma unroll
    for (int q = 0; q < 24; q++) sv[q] = 0.f;
#pragma unroll
    for (int c = 0; c < 4; c++){
        float4 w3 = *(const float4*)(W3s + (i4+c)*4);
#pragma unroll
        for (int pp = 0; pp < 4; pp++){
            float a0, a1; unpack2(acc[pp][c], a0, a1);
            int p0 = 2*pp, p1 = 2*pp+1;
            float d0 = g2[p0][c] * a0;
            float d1 = g2[p1][c] * a1;
            sv[p0*3+0] = fmaf(d0, w3.x, sv[p0*3+0]);
            sv[p0*3+1] = fmaf(d0, w3.y, sv[p0*3+1]);
            sv[p0*3+2] = fmaf(d0, w3.z, sv[p0*3+2]);
            sv[p1*3+0] = fmaf(d1, w3.x, sv[p1*3+0]);
            sv[p1*3+1] = fmaf(d1, w3.y, sv[p1*3+1]);
            sv[p1*3+2] = fmaf(d1, w3.z, sv[p1*3+2]);
        }
    }
    reduce24(sv);
    extract3(sv, lane, jx, jy, jz);
}

// ---- bucketing pre-pass (smem-aggregated counting sort) ----
__device__ __forceinline__ int steps_needed(float off){
    float a = fabsf(off);
    int k = (int)ceilf(a * 8.0f);
    return k > NSTEPS ? NSTEPS : k;
}

__global__ void k_zero(){
    if (threadIdx.x < 16){ g_hist[threadIdx.x] = 0; g_cursor[threadIdx.x] = 0; }
}
__global__ void k_hist(const float* __restrict__ t1, const float* __restrict__ t2, int n){
    __shared__ int lh[16];
    if (threadIdx.x < 16) lh[threadIdx.x] = 0;
    __syncthreads();
    int i = blockIdx.x*blockDim.x + threadIdx.x;
    if (i < n) atomicAdd(&lh[steps_needed(t1[i]-t2[i])], 1);
    __syncthreads();
    if (threadIdx.x < 16 && lh[threadIdx.x]) atomicAdd(&g_hist[threadIdx.x], lh[threadIdx.x]);
}
__global__ void k_prefix(){
    if (threadIdx.x == 0){
        int s = 0;
#pragma unroll
        for (int b = 0; b <= NSTEPS; b++){ g_cursor[b] = s; s += g_hist[b]; }
    }
}
__global__ void k_scatter(const float* __restrict__ t1, const float* __restrict__ t2, int n){
    __shared__ int lh[16], lbase[16];
    if (threadIdx.x < 16) lh[threadIdx.x] = 0;
    __syncthreads();
    int i = blockIdx.x*blockDim.x + threadIdx.x;
    int k = 0, loc = 0;
    bool v = (i < n);
    if (v){
        k = steps_needed(t1[i]-t2[i]);
        loc = atomicAdd(&lh[k], 1);
    }
    __syncthreads();
    if (threadIdx.x < 16 && lh[threadIdx.x])
        lbase[threadIdx.x] = atomicAdd(&g_cursor[threadIdx.x], lh[threadIdx.x]);
    __syncthreads();
    if (v) g_perm[lbase[k] + loc] = i;
}

__global__ void __launch_bounds__(THREADS, 1)
velwarp_kernel(const float* __restrict__ code_g, const float* __restrict__ pos_g,
               const float* __restrict__ t1_g, const float* __restrict__ t2_g,
               const float* __restrict__ W1_g, const float* __restrict__ b1_g,
               const float* __restrict__ W2_g, const float* __restrict__ b2_g,
               const float* __restrict__ W3_g, const float* __restrict__ b3_g,
               float* __restrict__ out, int n)
{
    extern __shared__ float sm[];
    const int tid  = threadIdx.x;
    const int w    = tid >> 5;
    const int lane = tid & 31;
    const int i4   = lane * 4;
    const int pbase = blockIdx.x * PPB;

    float* stg  = sm + SM_STG  + w * (HID*PPW);
    float* dstg = sm + SM_DSTG + w * (HID*PPW);
    float* wx   = sm + SM_WX   + w * (4*PPW);

    for (int idx = tid; idx < IN_DIM*HID; idx += THREADS) sm[SM_W1 + idx] = W1_g[idx];
    for (int idx = tid; idx < HID*HID;   idx += THREADS) sm[SM_W2 + idx] = W2_g[idx];
    if (tid < HID){
        sm[SM_B1 + tid] = b1_g[tid];
        sm[SM_B2 + tid] = b2_g[tid];
        sm[SM_W3 + tid*4 + 0] = W3_g[tid*3 + 0];
        sm[SM_W3 + tid*4 + 1] = W3_g[tid*3 + 1];
        sm[SM_W3 + tid*4 + 2] = W3_g[tid*3 + 2];
        sm[SM_W3 + tid*4 + 3] = 0.f;
    }
    if (tid < 4) sm[SM_B3 + tid] = (tid < 3) ? b3_g[tid] : 0.f;
    for (int idx = tid; idx < CODE_DIM*PPB; idx += THREADS){
        int p = idx >> 6;
        int k = idx & 63;
        int slot = pbase + p;
        int gp = (slot < n) ? g_perm[slot] : -1;
        sm[SM_CODE + k*PPB + p] = (gp >= 0) ? code_g[(size_t)gp*CODE_DIM + k] : 0.f;
    }
    __syncthreads();

    const float b3x = sm[SM_B3 + 0], b3y = sm[SM_B3 + 1], b3z = sm[SM_B3 + 2];

    const bool owner = (lane < PPW);
    const int  slot  = pbase + w*PPW + lane;
    const int  myp   = (owner && slot < n) ? g_perm[slot] : -1;
    const bool valid = (myp >= 0);

    float px=0.f, py=0.f, pz=0.f, tt=0.f, off=0.f;
    float D[9] = {1,0,0, 0,1,0, 0,0,1};
    if (valid){
        px  = pos_g[(size_t)myp*3 + 0];
        py  = pos_g[(size_t)myp*3 + 1];
        pz  = pos_g[(size_t)myp*3 + 2];
        tt  = t1_g[myp];
        off = tt - t2_g[myp];
    }

    float g2[8][4];
    float jac[9];

#pragma unroll 1
    for (int s = 0; s < NSTEPS; s++){
        if (__ballot_sync(0xffffffffu, off != 0.0f) == 0u) break;

        __syncwarp();
        if (owner){
            wx[0*PPW + lane] = px; wx[1*PPW + lane] = py;
            wx[2*PPW + lane] = pz; wx[3*PPW + lane] = tt;
        }
        __syncwarp();
        float vx, vy, vz;
        mlp_fwd8(sm, stg, wx, i4, w*PPW, lane, g2, b3x, b3y, b3z, vx, vy, vz);

        float dt = 0.f;
        __syncwarp();
        if (owner){
            dt = copysignf(fminf(fabsf(off), DT_MAXF), off);
            wx[0*PPW + lane] = fmaf(-0.5f*dt, vx, px);
            wx[1*PPW + lane] = fmaf(-0.5f*dt, vy, py);
            wx[2*PPW + lane] = fmaf(-0.5f*dt, vz, pz);
            wx[3*PPW + lane] = tt - 0.5f*dt;
        }
        __syncwarp();
        mlp_fwd8(sm, stg, wx, i4, w*PPW, lane, g2, b3x, b3y, b3z, vx, vy, vz);

#pragma unroll
        for (int j = 0; j < 3; j++){
            float jx, jy, jz;
            mlp_tan8(sm, stg, dstg, i4, j, lane, g2, jx, jy, jz);
            jac[j*3+0] = jx; jac[j*3+1] = jy; jac[j*3+2] = jz;
        }

        if (owner){
            float dr[9];
#pragma unroll
            for (int o = 0; o < 3; o++)
#pragma unroll
                for (int c = 0; c < 3; c++)
                    dr[o*3+c] = jac[0+o]*D[0*3+c] + jac[3+o]*D[1*3+c] + jac[6+o]*D[2*3+c];
#pragma unroll
            for (int q = 0; q < 9; q++) D[q] = fmaf(-dt, dr[q], D[q]);
            px = fmaf(-dt, vx, px);
            py = fmaf(-dt, vy, py);
            pz = fmaf(-dt, vz, pz);
            tt  -= dt;
            off -= dt;
        }
    }

    if (valid){
        out[(size_t)myp*3 + 0] = px;
        out[(size_t)myp*3 + 1] = py;
        out[(size_t)myp*3 + 2] = pz;
        float* od = out + (size_t)n*3 + (size_t)myp*9;
#pragma unroll
        for (int q = 0; q < 9; q++) od[q] = D[q];
    }
}

extern "C" void kernel_launch(void* const* d_in, const int* in_sizes, int n_in,
                              void* d_out, int out_size)
{
    const float* code = (const float*)d_in[0];
    const float* pos  = (const float*)d_in[1];
    const float* t1   = (const float*)d_in[2];
    const float* t2   = (const float*)d_in[3];
    const float* W1   = (const float*)d_in[4];
    const float* b1   = (const float*)d_in[5];
    const float* W2   = (const float*)d_in[6];
    const float* b2   = (const float*)d_in[7];
    const float* W3   = (const float*)d_in[8];
    const float* b3   = (const float*)d_in[9];

    const int n = in_sizes[2];
    const int blocks = (n + PPB - 1) / PPB;
    const size_t smem_bytes = (size_t)SM_TOTAL * sizeof(float);

    k_zero<<<1, 32>>>();
    k_hist<<<(n + 255)/256, 256>>>(t1, t2, n);
    k_prefix<<<1, 32>>>();
    k_scatter<<<(n + 255)/256, 256>>>(t1, t2, n);

    cudaFuncSetAttribute(velwarp_kernel,
                         cudaFuncAttributeMaxDynamicSharedMemorySize,
                         (int)smem_bytes);

    velwarp_kernel<<<blocks, THREADS, smem_bytes>>>(
        code, pos, t1, t2, W1, b1, W2, b2, W3, b3, (float*)d_out, n);
}

// round 5
// speedup vs baseline: 1.0289x; 1.0289x over previous
#include <cuda_runtime.h>
#include <cstdint>

#define CODE_DIM 64
#define IN_DIM   68
#define HID      128
#define DT_MAXF  0.125f
#define NSTEPS   8
#define THREADS  384
#define NWARPS   (THREADS/32)          // 12
#define PPW      8
#define PPB      (NWARPS*PPW)          // 96 points per block
#define MAXN     (1<<18)

typedef unsigned long long ull;

// ---- scratch for bucketing (no allocs allowed) ----
__device__ int g_hist[16];
__device__ int g_cursor[16];
__device__ int g_perm[MAXN];

// ---- shared memory layout (float offsets), 16B-aligned ----
#define SM_W1   0
#define SM_B1   (SM_W1 + IN_DIM*HID)          // 8704
#define SM_W2   (SM_B1 + HID)                 // 8832
#define SM_B2   (SM_W2 + HID*HID)             // 25216
#define SM_W3   (SM_B2 + HID)                 // 25344, padded [128][4]
#define SM_B3   (SM_W3 + HID*4)               // 25856
#define SM_W1X  (SM_B3 + 4)                   // 25860, [k][4] = {W1[64][k],W1[65][k],W1[66][k],0}
#define SM_PW   (SM_W1X + HID*4)              // 26372, per-warp regions
#define PW_SIZE (HID*PPW + HID*PPW + 4*PPW)   // stg 1024 + cpre 1024 + wx 32 = 2080
#define SM_TOTAL (SM_PW + NWARPS*PW_SIZE)     // 51332 floats = 205328 B

__device__ __forceinline__ float ftanh(float x){
    float e = __expf(2.0f * x);
    return 1.0f - __fdividef(2.0f, e + 1.0f);
}
__device__ __forceinline__ ull ffma2(ull a, ull b, ull c){
    ull d; asm("fma.rn.f32x2 %0, %1, %2, %3;" : "=l"(d) : "l"(a), "l"(b), "l"(c)); return d;
}
__device__ __forceinline__ ull fmul2(ull a, ull b){
    ull d; asm("mul.rn.f32x2 %0, %1, %2;" : "=l"(d) : "l"(a), "l"(b)); return d;
}
__device__ __forceinline__ ull pack2(float lo, float hi){
    ull d; asm("mov.b64 %0, {%1, %2};" : "=l"(d) : "f"(lo), "f"(hi)); return d;
}
__device__ __forceinline__ void unpack2(ull v, float& lo, float& hi){
    asm("mov.b64 {%0, %1}, %2;" : "=f"(lo), "=f"(hi) : "l"(v));
}

__device__ __forceinline__ void fma_step8(ull acc[4][4],
        const float* __restrict__ xrow, const float* __restrict__ wrow){
    ulonglong2 xa = *(const ulonglong2*)(xrow);
    ulonglong2 xb = *(const ulonglong2*)(xrow + 4);
    float4 wv = *(const float4*)(wrow);
    ull wd0 = pack2(wv.x, wv.x), wd1 = pack2(wv.y, wv.y);
    ull wd2 = pack2(wv.z, wv.z), wd3 = pack2(wv.w, wv.w);
    ull xp0 = xa.x, xp1 = xa.y, xp2 = xb.x, xp3 = xb.y;
    acc[0][0]=ffma2(xp0,wd0,acc[0][0]); acc[0][1]=ffma2(xp0,wd1,acc[0][1]);
    acc[0][2]=ffma2(xp0,wd2,acc[0][2]); acc[0][3]=ffma2(xp0,wd3,acc[0][3]);
    acc[1][0]=ffma2(xp1,wd0,acc[1][0]); acc[1][1]=ffma2(xp1,wd1,acc[1][1]);
    acc[1][2]=ffma2(xp1,wd2,acc[1][2]); acc[1][3]=ffma2(xp1,wd3,acc[1][3]);
    acc[2][0]=ffma2(xp2,wd0,acc[2][0]); acc[2][1]=ffma2(xp2,wd1,acc[2][1]);
    acc[2][2]=ffma2(xp2,wd2,acc[2][2]); acc[2][3]=ffma2(xp2,wd3,acc[2][3]);
    acc[3][0]=ffma2(xp3,wd0,acc[3][0]); acc[3][1]=ffma2(xp3,wd1,acc[3][1]);
    acc[3][2]=ffma2(xp3,wd2,acc[3][2]); acc[3][3]=ffma2(xp3,wd3,acc[3][3]);
}

__device__ __forceinline__ void acc_init_bias(ull acc[4][4], const float* bs, int i4){
    float4 bv = *(const float4*)(bs + i4);
    ull b0 = pack2(bv.x,bv.x), b1 = pack2(bv.y,bv.y);
    ull b2 = pack2(bv.z,bv.z), b3 = pack2(bv.w,bv.w);
#pragma unroll
    for (int pp = 0; pp < 4; pp++){ acc[pp][0]=b0; acc[pp][1]=b1; acc[pp][2]=b2; acc[pp][3]=b3; }
}

__device__ __forceinline__ void reduce_n(float* sv, int nq){
#pragma unroll
    for (int o = 16; o > 0; o >>= 1)
        for (int q = 0; q < nq; q++)
            sv[q] += __shfl_xor_sync(0xffffffffu, sv[q], o);
}

// forward MLP for 8 points. Layer-1 code part comes precomputed from cpre.
// Leaves h1 staged in stg [k][8]; returns g2=1-h2^2 and owner velocity.
__device__ __forceinline__ void mlp_fwd8(const float* __restrict__ sm,
        float* __restrict__ stg, const float* __restrict__ cpre,
        const float* __restrict__ wx,
        int i4, int lane, float g2[8][4],
        float b3x, float b3y, float b3z,
        float& vx, float& vy, float& vz)
{
    const float* W1s = sm + SM_W1;
    const float* W2s = sm + SM_W2;
    const float* W3s = sm + SM_W3;

    ull acc[4][4];
    // init from cpre (code contribution + b1), this lane's 4 hidden rows
#pragma unroll
    for (int c = 0; c < 4; c++){
        ulonglong2 a = *(const ulonglong2*)(cpre + (i4+c)*PPW);
        ulonglong2 b = *(const ulonglong2*)(cpre + (i4+c)*PPW + 4);
        acc[0][c]=a.x; acc[1][c]=a.y; acc[2][c]=b.x; acc[3][c]=b.y;
    }
#pragma unroll
    for (int kk = 0; kk < 4; kk++)
        fma_step8(acc, wx + kk*PPW, W1s + (CODE_DIM+kk)*HID + i4);

    // tanh + stage h1 to stg column-wise
    __syncwarp();
#pragma unroll
    for (int c = 0; c < 4; c++){
        float h0,h1v,h2v,h3,h4,h5,h6,h7;
        { float a,b; unpack2(acc[0][c],a,b); h0=ftanh(a); h1v=ftanh(b); }
        { float a,b; unpack2(acc[1][c],a,b); h2v=ftanh(a); h3=ftanh(b); }
        { float a,b; unpack2(acc[2][c],a,b); h4=ftanh(a); h5=ftanh(b); }
        { float a,b; unpack2(acc[3][c],a,b); h6=ftanh(a); h7=ftanh(b); }
        *(float4*)(stg + (i4+c)*PPW)     = make_float4(h0,h1v,h2v,h3);
        *(float4*)(stg + (i4+c)*PPW + 4) = make_float4(h4,h5,h6,h7);
    }
    __syncwarp();

    acc_init_bias(acc, sm + SM_B2, i4);
#pragma unroll 4
    for (int k = 0; k < HID; k++)
        fma_step8(acc, stg + k*PPW, W2s + k*HID + i4);

    float h2r[8][4];
#pragma unroll
    for (int pp = 0; pp < 4; pp++)
#pragma unroll
        for (int c = 0; c < 4; c++){
            float a, b; unpack2(acc[pp][c], a, b);
            h2r[2*pp  ][c] = ftanh(a);
            h2r[2*pp+1][c] = ftanh(b);
        }

    float sv[24];
#pragma unroll
    for (int q = 0; q < 24; q++) sv[q] = 0.f;
#pragma unroll
    for (int c = 0; c < 4; c++){
        float4 w3 = *(const float4*)(W3s + (i4+c)*4);
#pragma unroll
        for (int p = 0; p < 8; p++){
            sv[p*3+0] = fmaf(h2r[p][c], w3.x, sv[p*3+0]);
            sv[p*3+1] = fmaf(h2r[p][c], w3.y, sv[p*3+1]);
            sv[p*3+2] = fmaf(h2r[p][c], w3.z, sv[p*3+2]);
        }
    }
#pragma unroll
    for (int p = 0; p < 8; p++)
#pragma unroll
        for (int c = 0; c < 4; c++)
            g2[p][c] = fmaf(-h2r[p][c], h2r[p][c], 1.0f);

    reduce_n(sv, 24);
    float x=0.f,y=0.f,z=0.f;
#pragma unroll
    for (int p = 0; p < 8; p++){
        bool s = (lane == p);
        x = s ? sv[p*3+0] : x;
        y = s ? sv[p*3+1] : y;
        z = s ? sv[p*3+2] : z;
    }
    vx = x + b3x; vy = y + b3y; vz = z + b3z;
}

// ---- bucketing pre-pass (smem-aggregated counting sort) ----
__device__ __forceinline__ int steps_needed(float off){
    float a = fabsf(off);
    int k = (int)ceilf(a * 8.0f);
    return k > NSTEPS ? NSTEPS : k;
}
__global__ void k_zero(){
    if (threadIdx.x < 16){ g_hist[threadIdx.x] = 0; g_cursor[threadIdx.x] = 0; }
}
__global__ void k_hist(const float* __restrict__ t1, const float* __restrict__ t2, int n){
    __shared__ int lh[16];
    if (threadIdx.x < 16) lh[threadIdx.x] = 0;
    __syncthreads();
    int i = blockIdx.x*blockDim.x + threadIdx.x;
    if (i < n) atomicAdd(&lh[steps_needed(t1[i]-t2[i])], 1);
    __syncthreads();
    if (threadIdx.x < 16 && lh[threadIdx.x]) atomicAdd(&g_hist[threadIdx.x], lh[threadIdx.x]);
}
__global__ void k_prefix(){
    if (threadIdx.x == 0){
        int s = 0;
#pragma unroll
        for (int b = 0; b <= NSTEPS; b++){ g_cursor[b] = s; s += g_hist[b]; }
    }
}
__global__ void k_scatter(const float* __restrict__ t1, const float* __restrict__ t2, int n){
    __shared__ int lh[16], lbase[16];
    if (threadIdx.x < 16) lh[threadIdx.x] = 0;
    __syncthreads();
    int i = blockIdx.x*blockDim.x + threadIdx.x;
    int k = 0, loc = 0;
    bool v = (i < n);
    if (v){
        k = steps_needed(t1[i]-t2[i]);
        loc = atomicAdd(&lh[k], 1);
    }
    __syncthreads();
    if (threadIdx.x < 16 && lh[threadIdx.x])
        lbase[threadIdx.x] = atomicAdd(&g_cursor[threadIdx.x], lh[threadIdx.x]);
    __syncthreads();
    if (v) g_perm[lbase[k] + loc] = i;
}

__global__ void __launch_bounds__(THREADS, 1)
velwarp_kernel(const float* __restrict__ code_g, const float* __restrict__ pos_g,
               const float* __restrict__ t1_g, const float* __restrict__ t2_g,
               const float* __restrict__ W1_g, const float* __restrict__ b1_g,
               const float* __restrict__ W2_g, const float* __restrict__ b2_g,
               const float* __restrict__ W3_g, const float* __restrict__ b3_g,
               float* __restrict__ out, int n)
{
    extern __shared__ float sm[];
    const int tid  = threadIdx.x;
    const int w    = tid >> 5;
    const int lane = tid & 31;
    const int i4   = lane * 4;
    const int pbase = blockIdx.x * PPB;

    float* stg  = sm + SM_PW + w*PW_SIZE;
    float* cpre = stg + HID*PPW;
    float* wx   = cpre + HID*PPW;

    // ---- cooperative weight loads ----
    for (int idx = tid; idx < IN_DIM*HID; idx += THREADS) sm[SM_W1 + idx] = W1_g[idx];
    for (int idx = tid; idx < HID*HID;   idx += THREADS) sm[SM_W2 + idx] = W2_g[idx];
    if (tid < HID){
        sm[SM_B1 + tid] = b1_g[tid];
        sm[SM_B2 + tid] = b2_g[tid];
        sm[SM_W3 + tid*4 + 0] = W3_g[tid*3 + 0];
        sm[SM_W3 + tid*4 + 1] = W3_g[tid*3 + 1];
        sm[SM_W3 + tid*4 + 2] = W3_g[tid*3 + 2];
        sm[SM_W3 + tid*4 + 3] = 0.f;
        sm[SM_W1X + tid*4 + 0] = W1_g[(CODE_DIM+0)*HID + tid];
        sm[SM_W1X + tid*4 + 1] = W1_g[(CODE_DIM+1)*HID + tid];
        sm[SM_W1X + tid*4 + 2] = W1_g[(CODE_DIM+2)*HID + tid];
        sm[SM_W1X + tid*4 + 3] = 0.f;
    }
    if (tid < 4) sm[SM_B3 + tid] = (tid < 3) ? b3_g[tid] : 0.f;
    __syncthreads();

    const float b3x = sm[SM_B3 + 0], b3y = sm[SM_B3 + 1], b3z = sm[SM_B3 + 2];
    const float* W2s = sm + SM_W2;
    const float* W3s = sm + SM_W3;
    const float* w1x = sm + SM_W1X;

    const bool owner = (lane < PPW);
    const int  slot  = pbase + w*PPW + lane;
    const int  myp   = (owner && slot < n) ? g_perm[slot] : -1;
    const bool valid = (myp >= 0);

    // ---- per-warp: stage codes into stg [k][p] (k<64), then cpre = b1 + W1_code^T code ----
    {
        int p = lane >> 2;            // point 0..7
        int q = lane & 3;             // quarter 0..3
        int qslot = pbase + w*PPW + p;
        int qp = (qslot < n) ? g_perm[qslot] : -1;
        const float* cg = (qp >= 0) ? (code_g + (size_t)qp*CODE_DIM + q*16) : nullptr;
#pragma unroll
        for (int i = 0; i < 16; i += 4){
            float4 v = cg ? *(const float4*)(cg + i) : make_float4(0.f,0.f,0.f,0.f);
            stg[(q*16 + i + 0)*PPW + p] = v.x;
            stg[(q*16 + i + 1)*PPW + p] = v.y;
            stg[(q*16 + i + 2)*PPW + p] = v.z;
            stg[(q*16 + i + 3)*PPW + p] = v.w;
        }
        __syncwarp();
        ull acc[4][4];
        acc_init_bias(acc, sm + SM_B1, i4);
#pragma unroll 4
        for (int k = 0; k < CODE_DIM; k++)
            fma_step8(acc, stg + k*PPW, sm + SM_W1 + k*HID + i4);
#pragma unroll
        for (int c = 0; c < 4; c++){
            *(ulonglong2*)(cpre + (i4+c)*PPW)     = make_ulonglong2(acc[0][c], acc[1][c]);
            *(ulonglong2*)(cpre + (i4+c)*PPW + 4) = make_ulonglong2(acc[2][c], acc[3][c]);
        }
        __syncwarp();
    }

    float px=0.f, py=0.f, pz=0.f, tt=0.f, off=0.f;
    float D[9] = {1,0,0, 0,1,0, 0,0,1};
    if (valid){
        px  = pos_g[(size_t)myp*3 + 0];
        py  = pos_g[(size_t)myp*3 + 1];
        pz  = pos_g[(size_t)myp*3 + 2];
        tt  = t1_g[myp];
        off = tt - t2_g[myp];
    }

    float g2[8][4];
    float jac[9] = {0,0,0,0,0,0,0,0,0};

#pragma unroll 1
    for (int s = 0; s < NSTEPS; s++){
        if (__ballot_sync(0xffffffffu, off != 0.0f) == 0u) break;

        __syncwarp();
        if (owner){
            wx[0*PPW + lane] = px; wx[1*PPW + lane] = py;
            wx[2*PPW + lane] = pz; wx[3*PPW + lane] = tt;
        }
        __syncwarp();
        float vx, vy, vz;
        mlp_fwd8(sm, stg, cpre, wx, i4, lane, g2, b3x, b3y, b3z, vx, vy, vz);

        float dt = 0.f;
        __syncwarp();
        if (owner){
            dt = copysignf(fminf(fabsf(off), DT_MAXF), off);
            wx[0*PPW + lane] = fmaf(-0.5f*dt, vx, px);
            wx[1*PPW + lane] = fmaf(-0.5f*dt, vy, py);
            wx[2*PPW + lane] = fmaf(-0.5f*dt, vz, pz);
            wx[3*PPW + lane] = tt - 0.5f*dt;
        }
        __syncwarp();
        mlp_fwd8(sm, stg, cpre, wx, i4, lane, g2, b3x, b3y, b3z, vx, vy, vz);

        // convert stg in place: h1 -> g1 = 1 - h1^2 (this lane's 4 rows)
        __syncwarp();
#pragma unroll
        for (int c = 0; c < 4; c++){
            float4 ha = *(const float4*)(stg + (i4+c)*PPW);
            float4 hb = *(const float4*)(stg + (i4+c)*PPW + 4);
            ha.x = fmaf(-ha.x, ha.x, 1.f); ha.y = fmaf(-ha.y, ha.y, 1.f);
            ha.z = fmaf(-ha.z, ha.z, 1.f); ha.w = fmaf(-ha.w, ha.w, 1.f);
            hb.x = fmaf(-hb.x, hb.x, 1.f); hb.y = fmaf(-hb.y, hb.y, 1.f);
            hb.z = fmaf(-hb.z, hb.z, 1.f); hb.w = fmaf(-hb.w, hb.w, 1.f);
            *(float4*)(stg + (i4+c)*PPW)     = ha;
            *(float4*)(stg + (i4+c)*PPW + 4) = hb;
        }
        __syncwarp();

        // fused 3-direction tangent, 2 passes over 4-point halves
#pragma unroll
        for (int ph = 0; ph < 2; ph++){
            ull a0[2][4], a1[2][4], a2[2][4];
            ull zz = pack2(0.f, 0.f);
#pragma unroll
            for (int pp = 0; pp < 2; pp++)
#pragma unroll
                for (int c = 0; c < 4; c++){ a0[pp][c]=zz; a1[pp][c]=zz; a2[pp][c]=zz; }

#pragma unroll 4
            for (int k = 0; k < HID; k++){
                ulonglong2 g = *(const ulonglong2*)(stg + k*PPW + 4*ph);  // g1, 4 pts
                float4 wv = *(const float4*)(W2s + k*HID + i4);
                float4 wj = *(const float4*)(w1x + k*4);
                ull wd0=pack2(wv.x,wv.x), wd1=pack2(wv.y,wv.y);
                ull wd2=pack2(wv.z,wv.z), wd3=pack2(wv.w,wv.w);
                ull wj0=pack2(wj.x,wj.x), wj1=pack2(wj.y,wj.y), wj2=pack2(wj.z,wj.z);
                ull x00=fmul2(g.x,wj0), x01=fmul2(g.y,wj0);
                ull x10=fmul2(g.x,wj1), x11=fmul2(g.y,wj1);
                ull x20=fmul2(g.x,wj2), x21=fmul2(g.y,wj2);
                a0[0][0]=ffma2(x00,wd0,a0[0][0]); a0[0][1]=ffma2(x00,wd1,a0[0][1]);
                a0[0][2]=ffma2(x00,wd2,a0[0][2]); a0[0][3]=ffma2(x00,wd3,a0[0][3]);
                a0[1][0]=ffma2(x01,wd0,a0[1][0]); a0[1][1]=ffma2(x01,wd1,a0[1][1]);
                a0[1][2]=ffma2(x01,wd2,a0[1][2]); a0[1][3]=ffma2(x01,wd3,a0[1][3]);
                a1[0][0]=ffma2(x10,wd0,a1[0][0]); a1[0][1]=ffma2(x10,wd1,a1[0][1]);
                a1[0][2]=ffma2(x10,wd2,a1[0][2]); a1[0][3]=ffma2(x10,wd3,a1[0][3]);
                a1[1][0]=ffma2(x11,wd0,a1[1][0]); a1[1][1]=ffma2(x11,wd1,a1[1][1]);
                a1[1][2]=ffma2(x11,wd2,a1[1][2]); a1[1][3]=ffma2(x11,wd3,a1[1][3]);
                a2[0][0]=ffma2(x20,wd0,a2[0][0]); a2[0][1]=ffma2(x20,wd1,a2[0][1]);
                a2[0][2]=ffma2(x20,wd2,a2[0][2]); a2[0][3]=ffma2(x20,wd3,a2[0][3]);
                a2[1][0]=ffma2(x21,wd0,a2[1][0]); a2[1][1]=ffma2(x21,wd1,a2[1][1]);
                a2[1][2]=ffma2(x21,wd2,a2[1][2]); a2[1][3]=ffma2(x21,wd3,a2[1][3]);
            }

            // epilogue: sv[lp*9 + j*3 + o] for 4 local points
            float sv[36];
#pragma unroll
            for (int q = 0; q < 36; q++) sv[q] = 0.f;
#pragma unroll
            for (int c = 0; c < 4; c++){
                float4 w3 = *(const float4*)(W3s + (i4+c)*4);
#pragma unroll
                for (int pp = 0; pp < 2; pp++){
                    int gp0 = 4*ph + 2*pp, gp1 = gp0 + 1;
                    int l0 = 2*pp, l1 = l0 + 1;
                    float ba, bb;
                    unpack2(a0[pp][c], ba, bb);
                    { float d0 = g2[gp0][c]*ba, d1 = g2[gp1][c]*bb;
                      sv[l0*9+0]=fmaf(d0,w3.x,sv[l0*9+0]); sv[l0*9+1]=fmaf(d0,w3.y,sv[l0*9+1]); sv[l0*9+2]=fmaf(d0,w3.z,sv[l0*9+2]);
                      sv[l1*9+0]=fmaf(d1,w3.x,sv[l1*9+0]); sv[l1*9+1]=fmaf(d1,w3.y,sv[l1*9+1]); sv[l1*9+2]=fmaf(d1,w3.z,sv[l1*9+2]); }
                    unpack2(a1[pp][c], ba, bb);
                    { float d0 = g2[gp0][c]*ba, d1 = g2[gp1][c]*bb;
                      sv[l0*9+3]=fmaf(d0,w3.x,sv[l0*9+3]); sv[l0*9+4]=fmaf(d0,w3.y,sv[l0*9+4]); sv[l0*9+5]=fmaf(d0,w3.z,sv[l0*9+5]);
                      sv[l1*9+3]=fmaf(d1,w3.x,sv[l1*9+3]); sv[l1*9+4]=fmaf(d1,w3.y,sv[l1*9+4]); sv[l1*9+5]=fmaf(d1,w3.z,sv[l1*9+5]); }
                    unpack2(a2[pp][c], ba, bb);
                    { float d0 = g2[gp0][c]*ba, d1 = g2[gp1][c]*bb;
                      sv[l0*9+6]=fmaf(d0,w3.x,sv[l0*9+6]); sv[l0*9+7]=fmaf(d0,w3.y,sv[l0*9+7]); sv[l0*9+8]=fmaf(d0,w3.z,sv[l0*9+8]);
                      sv[l1*9+6]=fmaf(d1,w3.x,sv[l1*9+6]); sv[l1*9+7]=fmaf(d1,w3.y,sv[l1*9+7]); sv[l1*9+8]=fmaf(d1,w3.z,sv[l1*9+8]); }
                }
            }
            reduce_n(sv, 36);
            // owner lanes in this half extract their 9 jac values
            if (owner && ((lane >> 2) == ph)){
#pragma unroll
                for (int ii = 0; ii < 4; ii++){
                    bool sel = ((lane & 3) == ii);
#pragma unroll
                    for (int q = 0; q < 9; q++)
                        jac[q] = sel ? sv[ii*9 + q] : jac[q];
                }
            }
        }

        if (owner){
            // jac[j*3+o] = d v_o / d x_j ; drot[o][c] = sum_i jac_v[o][i]*D[i][c]
            float dr[9];
#pragma unroll
            for (int o = 0; o < 3; o++)
#pragma unroll
                for (int c = 0; c < 3; c++)
                    dr[o*3+c] = jac[0+o]*D[0*3+c] + jac[3+o]*D[1*3+c] + jac[6+o]*D[2*3+c];
#pragma unroll
            for (int q = 0; q < 9; q++) D[q] = fmaf(-dt, dr[q], D[q]);
            px = fmaf(-dt, vx, px);
            py = fmaf(-dt, vy, py);
            pz = fmaf(-dt, vz, pz);
            tt  -= dt;
            off -= dt;
        }
    }

    if (valid){
        out[(size_t)myp*3 + 0] = px;
        out[(size_t)myp*3 + 1] = py;
        out[(size_t)myp*3 + 2] = pz;
        float* od = out + (size_t)n*3 + (size_t)myp*9;
#pragma unroll
        for (int q = 0; q < 9; q++) od[q] = D[q];
    }
}

extern "C" void kernel_launch(void* const* d_in, const int* in_sizes, int n_in,
                              void* d_out, int out_size)
{
    const float* code = (const float*)d_in[0];
    const float* pos  = (const float*)d_in[1];
    const float* t1   = (const float*)d_in[2];
    const float* t2   = (const float*)d_in[3];
    const float* W1   = (const float*)d_in[4];
    const float* b1   = (const float*)d_in[5];
    const float* W2   = (const float*)d_in[6];
    const float* b2   = (const float*)d_in[7];
    const float* W3   = (const float*)d_in[8];
    const float* b3   = (const float*)d_in[9];

    const int n = in_sizes[2];
    const int blocks = (n + PPB - 1) / PPB;
    const size_t smem_bytes = (size_t)SM_TOTAL * sizeof(float);

    k_zero<<<1, 32>>>();
    k_hist<<<(n + 255)/256, 256>>>(t1, t2, n);
    k_prefix<<<1, 32>>>();
    k_scatter<<<(n + 255)/256, 256>>>(t1, t2, n);

    cudaFuncSetAttribute(velwarp_kernel,
                         cudaFuncAttributeMaxDynamicSharedMemorySize,
                         (int)smem_bytes);

    velwarp_kernel<<<blocks, THREADS, smem_bytes>>>(
        code, pos, t1, t2, W1, b1, W2, b2, W3, b3, (float*)d_out, n);
}

// round 6
// speedup vs baseline: 1.1147x; 1.0834x over previous
#include <cuda_runtime.h>
#include <cstdint>

#define CODE_DIM 64
#define IN_DIM   68
#define HID      128
#define DT_MAXF  0.125f
#define NSTEPS   8
#define THREADS  384
#define NWARPS   (THREADS/32)          // 12
#define PPW      8
#define PPB      (NWARPS*PPW)          // 96 points per block
#define MAXN     (1<<18)

typedef unsigned long long ull;

// ---- scratch for bucketing (no allocs allowed) ----
__device__ int g_hist[16];
__device__ int g_cursor[16];
__device__ int g_perm[MAXN];

// ---- shared memory layout (float offsets), 16B-aligned ----
#define SM_W1   0
#define SM_B1   (SM_W1 + IN_DIM*HID)          // 8704
#define SM_W2   (SM_B1 + HID)                 // 8832
#define SM_B2   (SM_W2 + HID*HID)             // 25216
#define SM_W3   (SM_B2 + HID)                 // 25344, padded [128][4]
#define SM_B3   (SM_W3 + HID*4)               // 25856
#define SM_W1X  (SM_B3 + 4)                   // 25860, [k][4] = {W1[64][k],W1[65][k],W1[66][k],0}
#define SM_PW   (SM_W1X + HID*4)              // 26372, per-warp regions
#define PW_SIZE (HID*PPW + HID*PPW + 4*PPW)   // stg 1024 + cpre 1024 + wx 32 = 2080
#define SM_TOTAL (SM_PW + NWARPS*PW_SIZE)     // 51332 floats = 205328 B

__device__ __forceinline__ float ftanh(float x){
    float e = __expf(2.0f * x);
    return 1.0f - __fdividef(2.0f, e + 1.0f);
}
__device__ __forceinline__ ull ffma2(ull a, ull b, ull c){
    ull d; asm("fma.rn.f32x2 %0, %1, %2, %3;" : "=l"(d) : "l"(a), "l"(b), "l"(c)); return d;
}
__device__ __forceinline__ ull fmul2(ull a, ull b){
    ull d; asm("mul.rn.f32x2 %0, %1, %2;" : "=l"(d) : "l"(a), "l"(b)); return d;
}
__device__ __forceinline__ ull pack2(float lo, float hi){
    ull d; asm("mov.b64 %0, {%1, %2};" : "=l"(d) : "f"(lo), "f"(hi)); return d;
}
__device__ __forceinline__ void unpack2(ull v, float& lo, float& hi){
    asm("mov.b64 {%0, %1}, %2;" : "=f"(lo), "=f"(hi) : "l"(v));
}

__device__ __forceinline__ void fma_step8(ull acc[4][4],
        const float* __restrict__ xrow, const float* __restrict__ wrow){
    ulonglong2 xa = *(const ulonglong2*)(xrow);
    ulonglong2 xb = *(const ulonglong2*)(xrow + 4);
    float4 wv = *(const float4*)(wrow);
    ull wd0 = pack2(wv.x, wv.x), wd1 = pack2(wv.y, wv.y);
    ull wd2 = pack2(wv.z, wv.z), wd3 = pack2(wv.w, wv.w);
    ull xp0 = xa.x, xp1 = xa.y, xp2 = xb.x, xp3 = xb.y;
    acc[0][0]=ffma2(xp0,wd0,acc[0][0]); acc[0][1]=ffma2(xp0,wd1,acc[0][1]);
    acc[0][2]=ffma2(xp0,wd2,acc[0][2]); acc[0][3]=ffma2(xp0,wd3,acc[0][3]);
    acc[1][0]=ffma2(xp1,wd0,acc[1][0]); acc[1][1]=ffma2(xp1,wd1,acc[1][1]);
    acc[1][2]=ffma2(xp1,wd2,acc[1][2]); acc[1][3]=ffma2(xp1,wd3,acc[1][3]);
    acc[2][0]=ffma2(xp2,wd0,acc[2][0]); acc[2][1]=ffma2(xp2,wd1,acc[2][1]);
    acc[2][2]=ffma2(xp2,wd2,acc[2][2]); acc[2][3]=ffma2(xp2,wd3,acc[2][3]);
    acc[3][0]=ffma2(xp3,wd0,acc[3][0]); acc[3][1]=ffma2(xp3,wd1,acc[3][1]);
    acc[3][2]=ffma2(xp3,wd2,acc[3][2]); acc[3][3]=ffma2(xp3,wd3,acc[3][3]);
}

__device__ __forceinline__ void acc_init_bias(ull acc[4][4], const float* bs, int i4){
    float4 bv = *(const float4*)(bs + i4);
    ull b0 = pack2(bv.x,bv.x), b1 = pack2(bv.y,bv.y);
    ull b2 = pack2(bv.z,bv.z), b3 = pack2(bv.w,bv.w);
#pragma unroll
    for (int pp = 0; pp < 4; pp++){ acc[pp][0]=b0; acc[pp][1]=b1; acc[pp][2]=b2; acc[pp][3]=b3; }
}

__device__ __forceinline__ void reduce_n(float* sv, int nq){
#pragma unroll
    for (int o = 16; o > 0; o >>= 1)
        for (int q = 0; q < nq; q++)
            sv[q] += __shfl_xor_sync(0xffffffffu, sv[q], o);
}

// forward MLP for 8 points. Layer-1 code part comes precomputed from cpre.
// Leaves h1 staged in stg [k][8]; returns g2=1-h2^2 and owner velocity.
__device__ __forceinline__ void mlp_fwd8(const float* __restrict__ sm,
        float* __restrict__ stg, const float* __restrict__ cpre,
        const float* __restrict__ wx,
        int i4, int lane, float g2[8][4],
        float b3x, float b3y, float b3z,
        float& vx, float& vy, float& vz)
{
    const float* W1s = sm + SM_W1;
    const float* W2s = sm + SM_W2;
    const float* W3s = sm + SM_W3;

    ull acc[4][4];
    // init from cpre (code contribution + b1), this lane's 4 hidden rows
#pragma unroll
    for (int c = 0; c < 4; c++){
        ulonglong2 a = *(const ulonglong2*)(cpre + (i4+c)*PPW);
        ulonglong2 b = *(const ulonglong2*)(cpre + (i4+c)*PPW + 4);
        acc[0][c]=a.x; acc[1][c]=a.y; acc[2][c]=b.x; acc[3][c]=b.y;
    }
#pragma unroll
    for (int kk = 0; kk < 4; kk++)
        fma_step8(acc, wx + kk*PPW, W1s + (CODE_DIM+kk)*HID + i4);

    // tanh + stage h1 to stg column-wise
    __syncwarp();
#pragma unroll
    for (int c = 0; c < 4; c++){
        float h0,h1v,h2v,h3,h4,h5,h6,h7;
        { float a,b; unpack2(acc[0][c],a,b); h0=ftanh(a); h1v=ftanh(b); }
        { float a,b; unpack2(acc[1][c],a,b); h2v=ftanh(a); h3=ftanh(b); }
        { float a,b; unpack2(acc[2][c],a,b); h4=ftanh(a); h5=ftanh(b); }
        { float a,b; unpack2(acc[3][c],a,b); h6=ftanh(a); h7=ftanh(b); }
        *(float4*)(stg + (i4+c)*PPW)     = make_float4(h0,h1v,h2v,h3);
        *(float4*)(stg + (i4+c)*PPW + 4) = make_float4(h4,h5,h6,h7);
    }
    __syncwarp();

    acc_init_bias(acc, sm + SM_B2, i4);
#pragma unroll 4
    for (int k = 0; k < HID; k++)
        fma_step8(acc, stg + k*PPW, W2s + k*HID + i4);

    float h2r[8][4];
#pragma unroll
    for (int pp = 0; pp < 4; pp++)
#pragma unroll
        for (int c = 0; c < 4; c++){
            float a, b; unpack2(acc[pp][c], a, b);
            h2r[2*pp  ][c] = ftanh(a);
            h2r[2*pp+1][c] = ftanh(b);
        }

    float sv[24];
#pragma unroll
    for (int q = 0; q < 24; q++) sv[q] = 0.f;
#pragma unroll
    for (int c = 0; c < 4; c++){
        float4 w3 = *(const float4*)(W3s + (i4+c)*4);
#pragma unroll
        for (int p = 0; p < 8; p++){
            sv[p*3+0] = fmaf(h2r[p][c], w3.x, sv[p*3+0]);
            sv[p*3+1] = fmaf(h2r[p][c], w3.y, sv[p*3+1]);
            sv[p*3+2] = fmaf(h2r[p][c], w3.z, sv[p*3+2]);
        }
    }
#pragma unroll
    for (int p = 0; p < 8; p++)
#pragma unroll
        for (int c = 0; c < 4; c++)
            g2[p][c] = fmaf(-h2r[p][c], h2r[p][c], 1.0f);

    reduce_n(sv, 24);
    float x=0.f,y=0.f,z=0.f;
#pragma unroll
    for (int p = 0; p < 8; p++){
        bool s = (lane == p);
        x = s ? sv[p*3+0] : x;
        y = s ? sv[p*3+1] : y;
        z = s ? sv[p*3+2] : z;
    }
    vx = x + b3x; vy = y + b3y; vz = z + b3z;
}

// ---- bucketing pre-pass (smem-aggregated counting sort) ----
__device__ __forceinline__ int steps_needed(float off){
    float a = fabsf(off);
    int k = (int)ceilf(a * 8.0f);
    return k > NSTEPS ? NSTEPS : k;
}
__global__ void k_zero(){
    if (threadIdx.x < 16){ g_hist[threadIdx.x] = 0; g_cursor[threadIdx.x] = 0; }
}
__global__ void k_hist(const float* __restrict__ t1, const float* __restrict__ t2, int n){
    __shared__ int lh[16];
    if (threadIdx.x < 16) lh[threadIdx.x] = 0;
    __syncthreads();
    int i = blockIdx.x*blockDim.x + threadIdx.x;
    if (i < n) atomicAdd(&lh[steps_needed(t1[i]-t2[i])], 1);
    __syncthreads();
    if (threadIdx.x < 16 && lh[threadIdx.x]) atomicAdd(&g_hist[threadIdx.x], lh[threadIdx.x]);
}
__global__ void k_prefix(){
    if (threadIdx.x == 0){
        int s = 0;
#pragma unroll
        for (int b = 0; b <= NSTEPS; b++){ g_cursor[b] = s; s += g_hist[b]; }
    }
}
__global__ void k_scatter(const float* __restrict__ t1, const float* __restrict__ t2, int n){
    __shared__ int lh[16], lbase[16];
    if (threadIdx.x < 16) lh[threadIdx.x] = 0;
    __syncthreads();
    int i = blockIdx.x*blockDim.x + threadIdx.x;
    int k = 0, loc = 0;
    bool v = (i < n);
    if (v){
        k = steps_needed(t1[i]-t2[i]);
        loc = atomicAdd(&lh[k], 1);
    }
    __syncthreads();
    if (threadIdx.x < 16 && lh[threadIdx.x])
        lbase[threadIdx.x] = atomicAdd(&g_cursor[threadIdx.x], lh[threadIdx.x]);
    __syncthreads();
    if (v) g_perm[lbase[k] + loc] = i;
}

__global__ void __launch_bounds__(THREADS, 1)
velwarp_kernel(const float* __restrict__ code_g, const float* __restrict__ pos_g,
               const float* __restrict__ t1_g, const float* __restrict__ t2_g,
               const float* __restrict__ W1_g, const float* __restrict__ b1_g,
               const float* __restrict__ W2_g, const float* __restrict__ b2_g,
               const float* __restrict__ W3_g, const float* __restrict__ b3_g,
               float* __restrict__ out, int n)
{
    extern __shared__ float sm[];
    const int tid  = threadIdx.x;
    const int w    = tid >> 5;
    const int lane = tid & 31;
    const int i4   = lane * 4;
    const int pbase = blockIdx.x * PPB;

    float* stg  = sm + SM_PW + w*PW_SIZE;
    float* cpre = stg + HID*PPW;
    float* wx   = cpre + HID*PPW;

    // ---- cooperative weight loads ----
    for (int idx = tid; idx < IN_DIM*HID; idx += THREADS) sm[SM_W1 + idx] = W1_g[idx];
    for (int idx = tid; idx < HID*HID;   idx += THREADS) sm[SM_W2 + idx] = W2_g[idx];
    if (tid < HID){
        sm[SM_B1 + tid] = b1_g[tid];
        sm[SM_B2 + tid] = b2_g[tid];
        sm[SM_W3 + tid*4 + 0] = W3_g[tid*3 + 0];
        sm[SM_W3 + tid*4 + 1] = W3_g[tid*3 + 1];
        sm[SM_W3 + tid*4 + 2] = W3_g[tid*3 + 2];
        sm[SM_W3 + tid*4 + 3] = 0.f;
        sm[SM_W1X + tid*4 + 0] = W1_g[(CODE_DIM+0)*HID + tid];
        sm[SM_W1X + tid*4 + 1] = W1_g[(CODE_DIM+1)*HID + tid];
        sm[SM_W1X + tid*4 + 2] = W1_g[(CODE_DIM+2)*HID + tid];
        sm[SM_W1X + tid*4 + 3] = 0.f;
    }
    if (tid < 4) sm[SM_B3 + tid] = (tid < 3) ? b3_g[tid] : 0.f;
    __syncthreads();

    const float b3x = sm[SM_B3 + 0], b3y = sm[SM_B3 + 1], b3z = sm[SM_B3 + 2];
    const float* W2s = sm + SM_W2;
    const float* W3s = sm + SM_W3;
    const float* w1x = sm + SM_W1X;

    const bool owner = (lane < PPW);
    const int  slot  = pbase + w*PPW + lane;
    const int  myp   = (owner && slot < n) ? g_perm[slot] : -1;
    const bool valid = (myp >= 0);

    // ---- per-warp: stage codes into stg [k][p] (k<64), then cpre = b1 + W1_code^T code ----
    {
        int p = lane >> 2;            // point 0..7
        int q = lane & 3;             // quarter 0..3
        int qslot = pbase + w*PPW + p;
        int qp = (qslot < n) ? g_perm[qslot] : -1;
        const float* cg = (qp >= 0) ? (code_g + (size_t)qp*CODE_DIM + q*16) : nullptr;
#pragma unroll
        for (int i = 0; i < 16; i += 4){
            float4 v = cg ? *(const float4*)(cg + i) : make_float4(0.f,0.f,0.f,0.f);
            stg[(q*16 + i + 0)*PPW + p] = v.x;
            stg[(q*16 + i + 1)*PPW + p] = v.y;
            stg[(q*16 + i + 2)*PPW + p] = v.z;
            stg[(q*16 + i + 3)*PPW + p] = v.w;
        }
        __syncwarp();
        ull acc[4][4];
        acc_init_bias(acc, sm + SM_B1, i4);
#pragma unroll 4
        for (int k = 0; k < CODE_DIM; k++)
            fma_step8(acc, stg + k*PPW, sm + SM_W1 + k*HID + i4);
#pragma unroll
        for (int c = 0; c < 4; c++){
            *(ulonglong2*)(cpre + (i4+c)*PPW)     = make_ulonglong2(acc[0][c], acc[1][c]);
            *(ulonglong2*)(cpre + (i4+c)*PPW + 4) = make_ulonglong2(acc[2][c], acc[3][c]);
        }
        __syncwarp();
    }

    float px=0.f, py=0.f, pz=0.f, tt=0.f, off=0.f;
    float D[9] = {1,0,0, 0,1,0, 0,0,1};
    if (valid){
        px  = pos_g[(size_t)myp*3 + 0];
        py  = pos_g[(size_t)myp*3 + 1];
        pz  = pos_g[(size_t)myp*3 + 2];
        tt  = t1_g[myp];
        off = tt - t2_g[myp];
    }

    float g2[8][4];
    float jac[9] = {0,0,0,0,0,0,0,0,0};

#pragma unroll 1
    for (int s = 0; s < NSTEPS; s++){
        if (__ballot_sync(0xffffffffu, off != 0.0f) == 0u) break;

        __syncwarp();
        if (owner){
            wx[0*PPW + lane] = px; wx[1*PPW + lane] = py;
            wx[2*PPW + lane] = pz; wx[3*PPW + lane] = tt;
        }
        __syncwarp();
        float vx, vy, vz;
        mlp_fwd8(sm, stg, cpre, wx, i4, lane, g2, b3x, b3y, b3z, vx, vy, vz);

        float dt = 0.f;
        __syncwarp();
        if (owner){
            dt = copysignf(fminf(fabsf(off), DT_MAXF), off);
            wx[0*PPW + lane] = fmaf(-0.5f*dt, vx, px);
            wx[1*PPW + lane] = fmaf(-0.5f*dt, vy, py);
            wx[2*PPW + lane] = fmaf(-0.5f*dt, vz, pz);
            wx[3*PPW + lane] = tt - 0.5f*dt;
        }
        __syncwarp();
        mlp_fwd8(sm, stg, cpre, wx, i4, lane, g2, b3x, b3y, b3z, vx, vy, vz);

        // convert stg in place: h1 -> g1 = 1 - h1^2 (this lane's 4 rows)
        __syncwarp();
#pragma unroll
        for (int c = 0; c < 4; c++){
            float4 ha = *(const float4*)(stg + (i4+c)*PPW);
            float4 hb = *(const float4*)(stg + (i4+c)*PPW + 4);
            ha.x = fmaf(-ha.x, ha.x, 1.f); ha.y = fmaf(-ha.y, ha.y, 1.f);
            ha.z = fmaf(-ha.z, ha.z, 1.f); ha.w = fmaf(-ha.w, ha.w, 1.f);
            hb.x = fmaf(-hb.x, hb.x, 1.f); hb.y = fmaf(-hb.y, hb.y, 1.f);
            hb.z = fmaf(-hb.z, hb.z, 1.f); hb.w = fmaf(-hb.w, hb.w, 1.f);
            *(float4*)(stg + (i4+c)*PPW)     = ha;
            *(float4*)(stg + (i4+c)*PPW + 4) = hb;
        }
        __syncwarp();

        // fused 3-direction tangent, 2 passes over 4-point halves
#pragma unroll
        for (int ph = 0; ph < 2; ph++){
            ull a0[2][4], a1[2][4], a2[2][4];
            ull zz = pack2(0.f, 0.f);
#pragma unroll
            for (int pp = 0; pp < 2; pp++)
#pragma unroll
                for (int c = 0; c < 4; c++){ a0[pp][c]=zz; a1[pp][c]=zz; a2[pp][c]=zz; }

#pragma unroll 4
            for (int k = 0; k < HID; k++){
                ulonglong2 g = *(const ulonglong2*)(stg + k*PPW + 4*ph);  // g1, 4 pts
                float4 wv = *(const float4*)(W2s + k*HID + i4);
                float4 wj = *(const float4*)(w1x + k*4);
                ull wd0=pack2(wv.x,wv.x), wd1=pack2(wv.y,wv.y);
                ull wd2=pack2(wv.z,wv.z), wd3=pack2(wv.w,wv.w);
                ull wj0=pack2(wj.x,wj.x), wj1=pack2(wj.y,wj.y), wj2=pack2(wj.z,wj.z);
                ull x00=fmul2(g.x,wj0), x01=fmul2(g.y,wj0);
                ull x10=fmul2(g.x,wj1), x11=fmul2(g.y,wj1);
                ull x20=fmul2(g.x,wj2), x21=fmul2(g.y,wj2);
                a0[0][0]=ffma2(x00,wd0,a0[0][0]); a0[0][1]=ffma2(x00,wd1,a0[0][1]);
                a0[0][2]=ffma2(x00,wd2,a0[0][2]); a0[0][3]=ffma2(x00,wd3,a0[0][3]);
                a0[1][0]=ffma2(x01,wd0,a0[1][0]); a0[1][1]=ffma2(x01,wd1,a0[1][1]);
                a0[1][2]=ffma2(x01,wd2,a0[1][2]); a0[1][3]=ffma2(x01,wd3,a0[1][3]);
                a1[0][0]=ffma2(x10,wd0,a1[0][0]); a1[0][1]=ffma2(x10,wd1,a1[0][1]);
                a1[0][2]=ffma2(x10,wd2,a1[0][2]); a1[0][3]=ffma2(x10,wd3,a1[0][3]);
                a1[1][0]=ffma2(x11,wd0,a1[1][0]); a1[1][1]=ffma2(x11,wd1,a1[1][1]);
                a1[1][2]=ffma2(x11,wd2,a1[1][2]); a1[1][3]=ffma2(x11,wd3,a1[1][3]);
                a2[0][0]=ffma2(x20,wd0,a2[0][0]); a2[0][1]=ffma2(x20,wd1,a2[0][1]);
                a2[0][2]=ffma2(x20,wd2,a2[0][2]); a2[0][3]=ffma2(x20,wd3,a2[0][3]);
                a2[1][0]=ffma2(x21,wd0,a2[1][0]); a2[1][1]=ffma2(x21,wd1,a2[1][1]);
                a2[1][2]=ffma2(x21,wd2,a2[1][2]); a2[1][3]=ffma2(x21,wd3,a2[1][3]);
            }

            // epilogue: sv[lp*9 + j*3 + o] for 4 local points
            float sv[36];
#pragma unroll
            for (int q = 0; q < 36; q++) sv[q] = 0.f;
#pragma unroll
            for (int c = 0; c < 4; c++){
                float4 w3 = *(const float4*)(W3s + (i4+c)*4);
#pragma unroll
                for (int pp = 0; pp < 2; pp++){
                    int gp0 = 4*ph + 2*pp, gp1 = gp0 + 1;
                    int l0 = 2*pp, l1 = l0 + 1;
                    float ba, bb;
                    unpack2(a0[pp][c], ba, bb);
                    { float d0 = g2[gp0][c]*ba, d1 = g2[gp1][c]*bb;
                      sv[l0*9+0]=fmaf(d0,w3.x,sv[l0*9+0]); sv[l0*9+1]=fmaf(d0,w3.y,sv[l0*9+1]); sv[l0*9+2]=fmaf(d0,w3.z,sv[l0*9+2]);
                      sv[l1*9+0]=fmaf(d1,w3.x,sv[l1*9+0]); sv[l1*9+1]=fmaf(d1,w3.y,sv[l1*9+1]); sv[l1*9+2]=fmaf(d1,w3.z,sv[l1*9+2]); }
                    unpack2(a1[pp][c], ba, bb);
                    { float d0 = g2[gp0][c]*ba, d1 = g2[gp1][c]*bb;
                      sv[l0*9+3]=fmaf(d0,w3.x,sv[l0*9+3]); sv[l0*9+4]=fmaf(d0,w3.y,sv[l0*9+4]); sv[l0*9+5]=fmaf(d0,w3.z,sv[l0*9+5]);
                      sv[l1*9+3]=fmaf(d1,w3.x,sv[l1*9+3]); sv[l1*9+4]=fmaf(d1,w3.y,sv[l1*9+4]); sv[l1*9+5]=fmaf(d1,w3.z,sv[l1*9+5]); }
                    unpack2(a2[pp][c], ba, bb);
                    { float d0 = g2[gp0][c]*ba, d1 = g2[gp1][c]*bb;
                      sv[l0*9+6]=fmaf(d0,w3.x,sv[l0*9+6]); sv[l0*9+7]=fmaf(d0,w3.y,sv[l0*9+7]); sv[l0*9+8]=fmaf(d0,w3.z,sv[l0*9+8]);
                      sv[l1*9+6]=fmaf(d1,w3.x,sv[l1*9+6]); sv[l1*9+7]=fmaf(d1,w3.y,sv[l1*9+7]); sv[l1*9+8]=fmaf(d1,w3.z,sv[l1*9+8]); }
                }
            }
            reduce_n(sv, 36);
            // owner lanes in this half extract their 9 jac values
            if (owner && ((lane >> 2) == ph)){
#pragma unroll
                for (int ii = 0; ii < 4; ii++){
                    bool sel = ((lane & 3) == ii);
#pragma unroll
                    for (int q = 0; q < 9; q++)
                        jac[q] = sel ? sv[ii*9 + q] : jac[q];
                }
            }
        }

        if (owner){
            // jac[j*3+o] = d v_o / d x_j ; drot[o][c] = sum_i jac_v[o][i]*D[i][c]
            float dr[9];
#pragma unroll
            for (int o = 0; o < 3; o++)
#pragma unroll
                for (int c = 0; c < 3; c++)
                    dr[o*3+c] = jac[0+o]*D[0*3+c] + jac[3+o]*D[1*3+c] + jac[6+o]*D[2*3+c];
#pragma unroll
            for (int q = 0; q < 9; q++) D[q] = fmaf(-dt, dr[q], D[q]);
            px = fmaf(-dt, vx, px);
            py = fmaf(-dt, vy, py);
            pz = fmaf(-dt, vz, pz);
            tt  -= dt;
            off -= dt;
        }
    }

    if (valid){
        out[(size_t)myp*3 + 0] = px;
        out[(size_t)myp*3 + 1] = py;
        out[(size_t)myp*3 + 2] = pz;
        float* od = out + (size_t)n*3 + (size_t)myp*9;
#pragma unroll
        for (int q = 0; q < 9; q++) od[q] = D[q];
    }
}

extern "C" void kernel_launch(void* const* d_in, const int* in_sizes, int n_in,
                              void* d_out, int out_size)
{
    const float* code = (const float*)d_in[0];
    const float* pos  = (const float*)d_in[1];
    const float* t1   = (const float*)d_in[2];
    const float* t2   = (const float*)d_in[3];
    const float* W1   = (const float*)d_in[4];
    const float* b1   = (const float*)d_in[5];
    const float* W2   = (const float*)d_in[6];
    const float* b2   = (const float*)d_in[7];
    const float* W3   = (const float*)d_in[8];
    const float* b3   = (const float*)d_in[9];

    const int n = in_sizes[2];
    const int blocks = (n + PPB - 1) / PPB;
    const size_t smem_bytes = (size_t)SM_TOTAL * sizeof(float);

    k_zero<<<1, 32>>>();
    k_hist<<<(n + 255)/256, 256>>>(t1, t2, n);
    k_prefix<<<1, 32>>>();
    k_scatter<<<(n + 255)/256, 256>>>(t1, t2, n);

    cudaFuncSetAttribute(velwarp_kernel,
                         cudaFuncAttributeMaxDynamicSharedMemorySize,
                         (int)smem_bytes);

    velwarp_kernel<<<blocks, THREADS, smem_bytes>>>(
        code, pos, t1, t2, W1, b1, W2, b2, W3, b3, (float*)d_out, n);
}

// round 8
// speedup vs baseline: 1.8823x; 1.6886x over previous
#include <cuda_runtime.h>
#include <cuda_bf16.h>
#include <cstdint>

#define HID 128
#define DT_MAXF 0.125f
#define NSTEPS 8
#define THREADS 256
#define MAXN (1<<18)
#define APITCH 272              // bytes per A row: 136 bf16 (128 data + 8 pad)

__device__ int g_hist[16];
__device__ int g_cursor[16];
__device__ int g_perm[MAXN];

// ---- smem byte offsets ----
#define OFF_AHI  0              // 34816: A hi bf16 [128][136]
#define OFF_ALO  34816          // 34816: A lo bf16 [128][136]
#define OFF_CPRE 69632          // 65536: cpre f32 [k][m]
#define OFF_PSUM 135168         // 53248: psum f32 [8 warps][128 m][13]
#define OFF_W1X  188416         // 2048 : f32 [k][4] = W1[64+q][k]
#define OFF_W3   190464         // 2048 : f32 [n][4]
#define OFF_B2   192512         // 512
#define OFF_WXS  193024         // 2048 : f32 [4][128]
#define SMEM_BYTES 195072

#define FCPRE (OFF_CPRE/4)
#define FPSUM (OFF_PSUM/4)
#define FW1X  (OFF_W1X/4)
#define FW3   (OFF_W3/4)
#define FB2   (OFF_B2/4)
#define FWXS  (OFF_WXS/4)
#define PSW   1664              // psum floats per warp (128*13)

__device__ __forceinline__ float ftanh(float x){
    float e = __expf(2.0f*x);
    return 1.0f - __fdividef(2.0f, e+1.0f);
}
__device__ __forceinline__ uint32_t packbf(float a, float b){
    __nv_bfloat162 t = __floats2bfloat162_rn(a, b);
    return *reinterpret_cast<uint32_t*>(&t);
}
__device__ __forceinline__ void splitbf(float v, float& hi, float& lo){
    hi = __bfloat162float(__float2bfloat16(v));
    lo = v - hi;
}
__device__ __forceinline__ void mma16816(float d[4], const uint32_t a[4], const uint32_t b[2]){
    asm volatile(
        "mma.sync.aligned.m16n8k16.row.col.f32.bf16.bf16.f32 "
        "{%0,%1,%2,%3}, {%4,%5,%6,%7}, {%8,%9}, {%0,%1,%2,%3};"
        : "+f"(d[0]), "+f"(d[1]), "+f"(d[2]), "+f"(d[3])
        : "r"(a[0]), "r"(a[1]), "r"(a[2]), "r"(a[3]), "r"(b[0]), "r"(b[1]));
}

// GEMM over A(smem bf16 hi/lo) x B(reg frags) with fused per-warp epilogue.
// MODE 0: v-epi (tanh(d+b2)*W3) -> psum cols pcol..pcol+2
// MODE 1: same + capture g2 = 1-h2^2 into g2f
// MODE 2: jac-epi ((d*g2)*W3)   -> psum cols pcol..pcol+2
template<int MODE>
__device__ __forceinline__ void gemm_epi(char* smc, float* smf,
        int g, int tig, int wslot, int pcol,
        const uint32_t (&bh)[2][8][2], const uint32_t (&bl)[2][8][2],
        float (&g2f)[64], const float (&b2r)[4], const float (&w3r)[4][3])
{
#pragma unroll
    for (int mt = 0; mt < 8; mt++){
        float d[2][4] = {{0.f,0.f,0.f,0.f},{0.f,0.f,0.f,0.f}};
        char* ah_base = smc + OFF_AHI + (mt*16+g)*APITCH + tig*4;
        char* al_base = smc + OFF_ALO + (mt*16+g)*APITCH + tig*4;
#pragma unroll
        for (int kt = 0; kt < 8; kt++){
            uint32_t ah[4], al[4];
            char* ph = ah_base + kt*32;
            char* pl = al_base + kt*32;
            ah[0]=*(uint32_t*)(ph);              ah[1]=*(uint32_t*)(ph+8*APITCH);
            ah[2]=*(uint32_t*)(ph+16);           ah[3]=*(uint32_t*)(ph+8*APITCH+16);
            al[0]=*(uint32_t*)(pl);              al[1]=*(uint32_t*)(pl+8*APITCH);
            al[2]=*(uint32_t*)(pl+16);           al[3]=*(uint32_t*)(pl+8*APITCH+16);
#pragma unroll
            for (int nt = 0; nt < 2; nt++){
                mma16816(d[nt], ah, bh[nt][kt]);
                mma16816(d[nt], al, bh[nt][kt]);
                mma16816(d[nt], ah, bl[nt][kt]);
            }
        }
        float s[2][3] = {{0.f,0.f,0.f},{0.f,0.f,0.f}};
#pragma unroll
        for (int nt = 0; nt < 2; nt++)
#pragma unroll
        for (int idx = 0; idx < 4; idx++){
            int cj = nt*2 + (idx&1);
            int rh = idx>>1;
            float val = d[nt][idx];
            float use;
            if (MODE < 2){
                float hv = ftanh(val + b2r[cj]);
                if (MODE == 1) g2f[mt*8 + nt*4 + idx] = fmaf(-hv, hv, 1.f);
                use = hv;
            } else {
                use = val * g2f[mt*8 + nt*4 + idx];
            }
            s[rh][0] = fmaf(use, w3r[cj][0], s[rh][0]);
            s[rh][1] = fmaf(use, w3r[cj][1], s[rh][1]);
            s[rh][2] = fmaf(use, w3r[cj][2], s[rh][2]);
        }
#pragma unroll
        for (int rh = 0; rh < 2; rh++)
#pragma unroll
        for (int o = 0; o < 3; o++){
            float v = s[rh][o];
            v += __shfl_xor_sync(0xffffffffu, v, 1);
            v += __shfl_xor_sync(0xffffffffu, v, 2);
            s[rh][o] = v;
        }
        if (tig == 0){
            int row = mt*16 + g;
            float* p0 = smf + FPSUM + wslot*PSW + row*13 + pcol;
            p0[0]=s[0][0]; p0[1]=s[0][1]; p0[2]=s[0][2];
            float* p1 = p0 + 8*13;
            p1[0]=s[1][0]; p1[1]=s[1][1]; p1[2]=s[1][2];
        }
    }
}

// ---- bucketing (counting sort by needed step count) ----
__device__ __forceinline__ int steps_needed(float off){
    float a = fabsf(off);
    int k = (int)ceilf(a*8.0f);
    return k > NSTEPS ? NSTEPS : k;
}
__global__ void k_zero(){ if (threadIdx.x<16){ g_hist[threadIdx.x]=0; g_cursor[threadIdx.x]=0; } }
__global__ void k_hist(const float* t1, const float* t2, int n){
    __shared__ int lh[16];
    if (threadIdx.x<16) lh[threadIdx.x]=0;
    __syncthreads();
    int i = blockIdx.x*blockDim.x + threadIdx.x;
    if (i<n) atomicAdd(&lh[steps_needed(t1[i]-t2[i])],1);
    __syncthreads();
    if (threadIdx.x<16 && lh[threadIdx.x]) atomicAdd(&g_hist[threadIdx.x], lh[threadIdx.x]);
}
__global__ void k_prefix(){
    if (threadIdx.x==0){ int s=0;
#pragma unroll
        for (int b=0;b<=NSTEPS;b++){ g_cursor[b]=s; s+=g_hist[b]; } }
}
__global__ void k_scatter(const float* t1, const float* t2, int n){
    __shared__ int lh[16], lb[16];
    if (threadIdx.x<16) lh[threadIdx.x]=0;
    __syncthreads();
    int i = blockIdx.x*blockDim.x + threadIdx.x;
    int k=0, loc=0; bool v = (i<n);
    if (v){ k = steps_needed(t1[i]-t2[i]); loc = atomicAdd(&lh[k],1); }
    __syncthreads();
    if (threadIdx.x<16 && lh[threadIdx.x]) lb[threadIdx.x]=atomicAdd(&g_cursor[threadIdx.x], lh[threadIdx.x]);
    __syncthreads();
    if (v) g_perm[lb[k]+loc] = i;
}

__global__ void __launch_bounds__(THREADS, 1)
velwarp_kernel(const float* __restrict__ code_g, const float* __restrict__ pos_g,
               const float* __restrict__ t1_g, const float* __restrict__ t2_g,
               const float* __restrict__ W1_g, const float* __restrict__ b1_g,
               const float* __restrict__ W2_g, const float* __restrict__ b2_g,
               const float* __restrict__ W3_g, const float* __restrict__ b3_g,
               float* __restrict__ out, int n)
{
    extern __shared__ char smc[];
    float* smf = (float*)smc;
    const int tid  = threadIdx.x;
    const int lane = tid & 31;
    const int g    = lane >> 2;          // mma group id
    const int tig  = lane & 3;           // thread in group
    const int wslot = tid >> 5;          // warp 0..7; owns output cols 16w..16w+15
    const int nbase = wslot * 16;
    const int m    = tid & 127;          // point in CTA
    const int kb   = (tid >> 7) * 64;    // hidden k half
    const bool owner = (tid < 128);
    const int pbase = blockIdx.x * 128;
    const int slot = pbase + m;
    const int myp = (slot < n) ? g_perm[slot] : -1;

    // ---- prologue: stage W1 (f32) into A region temporarily ----
    {
        float* w1tmp = (float*)(smc + OFF_AHI);
        for (int i = tid; i < 64*HID; i += THREADS) w1tmp[i] = W1_g[i];
        if (tid < HID){
#pragma unroll
            for (int kk=0;kk<4;kk++) smf[FW1X + tid*4 + kk] = W1_g[(64+kk)*HID + tid];
            smf[FW3 + tid*4 + 0] = W3_g[tid*3+0];
            smf[FW3 + tid*4 + 1] = W3_g[tid*3+1];
            smf[FW3 + tid*4 + 2] = W3_g[tid*3+2];
            smf[FW3 + tid*4 + 3] = 0.f;
            smf[FB2 + tid] = b2_g[tid];
        }
        __syncthreads();
        // cpre[k][m] = b1[k] + sum_c code[m][c]*W1[c][k], this thread's 64 k's
        float coder[64];
#pragma unroll
        for (int i=0;i<64;i+=4){
            float4 v = (myp>=0) ? *(const float4*)(code_g + (size_t)myp*64 + i)
                                : make_float4(0.f,0.f,0.f,0.f);
            coder[i]=v.x; coder[i+1]=v.y; coder[i+2]=v.z; coder[i+3]=v.w;
        }
        float acc[64];
#pragma unroll
        for (int i=0;i<64;i++) acc[i] = b1_g[kb+i];
        for (int c=0;c<64;c++){
            float cc = coder[c];
            const float* wr = w1tmp + c*HID + kb;
#pragma unroll
            for (int i=0;i<64;i+=4){
                float4 w = *(const float4*)(wr + i);
                acc[i]   = fmaf(cc,w.x,acc[i]);
                acc[i+1] = fmaf(cc,w.y,acc[i+1]);
                acc[i+2] = fmaf(cc,w.z,acc[i+2]);
                acc[i+3] = fmaf(cc,w.w,acc[i+3]);
            }
        }
#pragma unroll
        for (int i=0;i<64;i++) smf[FCPRE + (kb+i)*128 + m] = acc[i];
        __syncthreads();   // A region free from here
    }

    // ---- preload W2 fragments (hi/lo) into registers ----
    uint32_t bh[2][8][2], bl[2][8][2];
#pragma unroll
    for (int nt=0;nt<2;nt++)
#pragma unroll
    for (int kt=0;kt<8;kt++){
        int nn = nbase + nt*8 + g;
        int k0 = kt*16 + tig*2;
        float f0=W2_g[(size_t)k0*HID+nn],     f1=W2_g[(size_t)(k0+1)*HID+nn];
        float f2=W2_g[(size_t)(k0+8)*HID+nn], f3=W2_g[(size_t)(k0+9)*HID+nn];
        float h0,l0,h1,l1,h2,l2,h3,l3;
        splitbf(f0,h0,l0); splitbf(f1,h1,l1); splitbf(f2,h2,l2); splitbf(f3,h3,l3);
        bh[nt][kt][0]=packbf(h0,h1); bh[nt][kt][1]=packbf(h2,h3);
        bl[nt][kt][0]=packbf(l0,l1); bl[nt][kt][1]=packbf(l2,l3);
    }
    // per-thread epilogue constants for this warp's 4 columns
    float b2r[4]; float w3r[4][3];
#pragma unroll
    for (int cj=0;cj<4;cj++){
        int nn = nbase + (cj>>1)*8 + tig*2 + (cj&1);
        b2r[cj] = smf[FB2+nn];
        w3r[cj][0]=smf[FW3+nn*4+0];
        w3r[cj][1]=smf[FW3+nn*4+1];
        w3r[cj][2]=smf[FW3+nn*4+2];
    }
    const float b3x=b3_g[0], b3y=b3_g[1], b3z=b3_g[2];

    float px=0.f,py=0.f,pz=0.f,tt=0.f,off=0.f;
    float D[9] = {1,0,0, 0,1,0, 0,0,1};
    if (owner && myp>=0){
        px = pos_g[(size_t)myp*3+0];
        py = pos_g[(size_t)myp*3+1];
        pz = pos_g[(size_t)myp*3+2];
        tt = t1_g[myp];
        off = tt - t2_g[myp];
    }

    float h[64], g2f[64];

#define LAYER1() do { \
        float x0=smf[FWXS+m], x1=smf[FWXS+128+m], x2=smf[FWXS+256+m], x3=smf[FWXS+384+m]; \
        _Pragma("unroll") \
        for (int i=0;i<64;i++){ \
            float a = smf[FCPRE + (kb+i)*128 + m]; \
            float4 w = *(const float4*)(smf + FW1X + (kb+i)*4); \
            a=fmaf(x0,w.x,a); a=fmaf(x1,w.y,a); a=fmaf(x2,w.z,a); a=fmaf(x3,w.w,a); \
            h[i] = ftanh(a); \
        } \
    } while(0)
#define STAGE_H() do { \
        _Pragma("unroll") \
        for (int p=0;p<32;p++){ \
            float a,b,c,dd; splitbf(h[2*p],a,b); splitbf(h[2*p+1],c,dd); \
            *(uint32_t*)(smc + OFF_AHI + m*APITCH + (kb+2*p)*2) = packbf(a,c); \
            *(uint32_t*)(smc + OFF_ALO + m*APITCH + (kb+2*p)*2) = packbf(b,dd); \
        } \
    } while(0)
#define STAGE_TAN(J) do { \
        _Pragma("unroll") \
        for (int p=0;p<32;p++){ \
            float d0 = h[2*p]   * smf[FW1X + (kb+2*p)*4   + (J)]; \
            float d1 = h[2*p+1] * smf[FW1X + (kb+2*p+1)*4 + (J)]; \
            float a,b,c,dd; splitbf(d0,a,b); splitbf(d1,c,dd); \
            *(uint32_t*)(smc + OFF_AHI + m*APITCH + (kb+2*p)*2) = packbf(a,c); \
            *(uint32_t*)(smc + OFF_ALO + m*APITCH + (kb+2*p)*2) = packbf(b,dd); \
        } \
    } while(0)
#define OWNER_SUM(col) ({ \
        float _s = 0.f; \
        _Pragma("unroll") \
        for (int ww=0; ww<8; ww++) _s += smf[FPSUM + ww*PSW + m*13 + (col)]; \
        _s; })

#pragma unroll 1
    for (int s = 0; s < NSTEPS; s++){
        if (!__syncthreads_or(owner && off != 0.0f)) break;
        if (owner){ smf[FWXS+m]=px; smf[FWXS+128+m]=py; smf[FWXS+256+m]=pz; smf[FWXS+384+m]=tt; }
        __syncthreads();

        // ---- fwd1 ----
        LAYER1(); STAGE_H();
        __syncthreads();
        gemm_epi<0>(smc, smf, g, tig, wslot, 0, bh, bl, g2f, b2r, w3r);
        __syncthreads();
        float dt = 0.f;
        if (owner){
            dt = copysignf(fminf(fabsf(off), DT_MAXF), off);
            float v1x = OWNER_SUM(0)+b3x, v1y = OWNER_SUM(1)+b3y, v1z = OWNER_SUM(2)+b3z;
            smf[FWXS+m]     = fmaf(-0.5f*dt, v1x, px);
            smf[FWXS+128+m] = fmaf(-0.5f*dt, v1y, py);
            smf[FWXS+256+m] = fmaf(-0.5f*dt, v1z, pz);
            smf[FWXS+384+m] = tt - 0.5f*dt;
        }
        __syncthreads();

        // ---- fwd2 (captures g2 fragments) ----
        LAYER1(); STAGE_H();
        __syncthreads();
        gemm_epi<1>(smc, smf, g, tig, wslot, 0, bh, bl, g2f, b2r, w3r);
        __syncthreads();
        float vx=0.f, vy=0.f, vz=0.f;
        if (owner){ vx = OWNER_SUM(0)+b3x; vy = OWNER_SUM(1)+b3y; vz = OWNER_SUM(2)+b3z; }
        // h -> g1 in place
#pragma unroll
        for (int i=0;i<64;i++) h[i] = fmaf(-h[i], h[i], 1.f);

        // ---- tangents: psum cols j*3..j*3+2 ----
#pragma unroll 1
        for (int j=0;j<3;j++){
            STAGE_TAN(j);
            __syncthreads();
            gemm_epi<2>(smc, smf, g, tig, wslot, j*3, bh, bl, g2f, b2r, w3r);
            __syncthreads();
        }
        if (owner){
            float jac[9];
#pragma unroll
            for (int q=0;q<9;q++) jac[q] = OWNER_SUM(q);
            float dr[9];
#pragma unroll
            for (int o=0;o<3;o++)
#pragma unroll
                for (int c=0;c<3;c++)
                    dr[o*3+c] = jac[0+o]*D[0*3+c] + jac[3+o]*D[1*3+c] + jac[6+o]*D[2*3+c];
#pragma unroll
            for (int q=0;q<9;q++) D[q] = fmaf(-dt, dr[q], D[q]);
            px = fmaf(-dt, vx, px);
            py = fmaf(-dt, vy, py);
            pz = fmaf(-dt, vz, pz);
            tt -= dt; off -= dt;
        }
    }

    if (owner && myp >= 0){
        out[(size_t)myp*3+0]=px; out[(size_t)myp*3+1]=py; out[(size_t)myp*3+2]=pz;
        float* od = out + (size_t)n*3 + (size_t)myp*9;
#pragma unroll
        for (int q=0;q<9;q++) od[q] = D[q];
    }
}

extern "C" void kernel_launch(void* const* d_in, const int* in_sizes, int n_in,
                              void* d_out, int out_size)
{
    const float* code = (const float*)d_in[0];
    const float* pos  = (const float*)d_in[1];
    const float* t1   = (const float*)d_in[2];
    const float* t2   = (const float*)d_in[3];
    const float* W1   = (const float*)d_in[4];
    const float* b1   = (const float*)d_in[5];
    const float* W2   = (const float*)d_in[6];
    const float* b2   = (const float*)d_in[7];
    const float* W3   = (const float*)d_in[8];
    const float* b3   = (const float*)d_in[9];
    const int n = in_sizes[2];

    k_zero<<<1,32>>>();
    k_hist<<<(n+255)/256,256>>>(t1,t2,n);
    k_prefix<<<1,32>>>();
    k_scatter<<<(n+255)/256,256>>>(t1,t2,n);

    cudaFuncSetAttribute(velwarp_kernel,
                         cudaFuncAttributeMaxDynamicSharedMemorySize, SMEM_BYTES);
    velwarp_kernel<<<(n+127)/128, THREADS, SMEM_BYTES>>>(
        code, pos, t1, t2, W1, b1, W2, b2, W3, b3, (float*)d_out, n);
}